// round 1
// baseline (speedup 1.0000x reference)
#include <cuda_runtime.h>
#include <math.h>

#define BM 128
#define BN 128
#define BK 8
#define PAD 4

#define NB  16
#define SEQ 1024
#define HID 768
#define SCALE 0.03608439182435161f  /* 1/sqrt(768) */

// Scratch (device globals: allocation-free per harness rules)
__device__ float g_q [(size_t)NB*SEQ*HID];
__device__ float g_k [(size_t)NB*SEQ*HID];
__device__ float g_v [(size_t)NB*SEQ*HID];
__device__ float g_sc[(size_t)NB*SEQ*SEQ];
__device__ float g_o [(size_t)NB*SEQ*HID];
__device__ float g_h1[(size_t)NB*SEQ*HID];

// ---------------------------------------------------------------------------
// NT GEMM: C[M,N] = act(A[M,K] * W[N,K]^T + bias) (+ res). All dims % tile == 0.
// ---------------------------------------------------------------------------
__global__ __launch_bounds__(256) void gemm_nt_kernel(
    const float* __restrict__ A, const float* __restrict__ W,
    const float* __restrict__ bias, const float* __restrict__ res,
    float* __restrict__ C, int M, int N, int K, int relu)
{
    __shared__ float As[BK][BM + PAD];
    __shared__ float Bs[BK][BN + PAD];

    const int bm = blockIdx.y * BM;
    const int bn = blockIdx.x * BN;
    const int tid = threadIdx.x;

    const int ldrow = tid >> 1;          // 0..127
    const int ldk   = (tid & 1) << 2;    // 0 or 4
    const float* Ap = A + (size_t)(bm + ldrow) * K + ldk;
    const float* Wp = W + (size_t)(bn + ldrow) * K + ldk;

    const int ty = tid >> 4;             // 0..15 -> rows ty*8..ty*8+7
    const int tx = tid & 15;             // cols tx + j*16

    float acc[8][8];
    #pragma unroll
    for (int i = 0; i < 8; i++)
        #pragma unroll
        for (int j = 0; j < 8; j++) acc[i][j] = 0.f;

    for (int k0 = 0; k0 < K; k0 += BK) {
        float4 av = *reinterpret_cast<const float4*>(Ap + k0);
        float4 wv = *reinterpret_cast<const float4*>(Wp + k0);
        As[ldk+0][ldrow] = av.x; As[ldk+1][ldrow] = av.y;
        As[ldk+2][ldrow] = av.z; As[ldk+3][ldrow] = av.w;
        Bs[ldk+0][ldrow] = wv.x; Bs[ldk+1][ldrow] = wv.y;
        Bs[ldk+2][ldrow] = wv.z; Bs[ldk+3][ldrow] = wv.w;
        __syncthreads();

        #pragma unroll
        for (int kk = 0; kk < BK; kk++) {
            float a[8], b[8];
            float4 a0 = *reinterpret_cast<const float4*>(&As[kk][ty*8]);
            float4 a1 = *reinterpret_cast<const float4*>(&As[kk][ty*8+4]);
            a[0]=a0.x; a[1]=a0.y; a[2]=a0.z; a[3]=a0.w;
            a[4]=a1.x; a[5]=a1.y; a[6]=a1.z; a[7]=a1.w;
            #pragma unroll
            for (int j = 0; j < 8; j++) b[j] = Bs[kk][tx + j*16];
            #pragma unroll
            for (int i = 0; i < 8; i++)
                #pragma unroll
                for (int j = 0; j < 8; j++)
                    acc[i][j] = fmaf(a[i], b[j], acc[i][j]);
        }
        __syncthreads();
    }

    #pragma unroll
    for (int i = 0; i < 8; i++) {
        const int row = bm + ty*8 + i;
        float* Crow = C + (size_t)row * N;
        const float* Rrow = res ? (res + (size_t)row * N) : nullptr;
        #pragma unroll
        for (int j = 0; j < 8; j++) {
            const int col = bn + tx + j*16;
            float v = acc[i][j] + bias[col];
            if (relu) v = fmaxf(v, 0.f);
            if (Rrow) v += Rrow[col];
            Crow[col] = v;
        }
    }
}

// ---------------------------------------------------------------------------
// Batched score GEMM: S[b,s,t] = (q[b,s,:].k[b,t,:])*SCALE - (1-m_s*m_t)*1e12
// ---------------------------------------------------------------------------
__global__ __launch_bounds__(256) void score_gemm_kernel(
    const float* __restrict__ Q, const float* __restrict__ Kt,
    const int* __restrict__ mask, float* __restrict__ Sc)
{
    __shared__ float As[BK][BM + PAD];
    __shared__ float Bs[BK][BN + PAD];

    const int b  = blockIdx.z;
    const float* A = Q  + (size_t)b * SEQ * HID;
    const float* W = Kt + (size_t)b * SEQ * HID;
    float* C = Sc + (size_t)b * SEQ * SEQ;
    const int* mrow = mask + (size_t)b * SEQ;

    const int bm = blockIdx.y * BM;
    const int bn = blockIdx.x * BN;
    const int tid = threadIdx.x;
    const int ldrow = tid >> 1;
    const int ldk   = (tid & 1) << 2;
    const float* Ap = A + (size_t)(bm + ldrow) * HID + ldk;
    const float* Wp = W + (size_t)(bn + ldrow) * HID + ldk;
    const int ty = tid >> 4;
    const int tx = tid & 15;

    float acc[8][8];
    #pragma unroll
    for (int i = 0; i < 8; i++)
        #pragma unroll
        for (int j = 0; j < 8; j++) acc[i][j] = 0.f;

    for (int k0 = 0; k0 < HID; k0 += BK) {
        float4 av = *reinterpret_cast<const float4*>(Ap + k0);
        float4 wv = *reinterpret_cast<const float4*>(Wp + k0);
        As[ldk+0][ldrow] = av.x; As[ldk+1][ldrow] = av.y;
        As[ldk+2][ldrow] = av.z; As[ldk+3][ldrow] = av.w;
        Bs[ldk+0][ldrow] = wv.x; Bs[ldk+1][ldrow] = wv.y;
        Bs[ldk+2][ldrow] = wv.z; Bs[ldk+3][ldrow] = wv.w;
        __syncthreads();
        #pragma unroll
        for (int kk = 0; kk < BK; kk++) {
            float a[8], bb[8];
            float4 a0 = *reinterpret_cast<const float4*>(&As[kk][ty*8]);
            float4 a1 = *reinterpret_cast<const float4*>(&As[kk][ty*8+4]);
            a[0]=a0.x; a[1]=a0.y; a[2]=a0.z; a[3]=a0.w;
            a[4]=a1.x; a[5]=a1.y; a[6]=a1.z; a[7]=a1.w;
            #pragma unroll
            for (int j = 0; j < 8; j++) bb[j] = Bs[kk][tx + j*16];
            #pragma unroll
            for (int i = 0; i < 8; i++)
                #pragma unroll
                for (int j = 0; j < 8; j++)
                    acc[i][j] = fmaf(a[i], bb[j], acc[i][j]);
        }
        __syncthreads();
    }

    float mr[8], mc[8];
    #pragma unroll
    for (int i = 0; i < 8; i++) mr[i] = (float)mrow[bm + ty*8 + i];
    #pragma unroll
    for (int j = 0; j < 8; j++) mc[j] = (float)mrow[bn + tx + j*16];

    #pragma unroll
    for (int i = 0; i < 8; i++) {
        const int row = bm + ty*8 + i;
        float* Crow = C + (size_t)row * SEQ;
        #pragma unroll
        for (int j = 0; j < 8; j++) {
            const int col = bn + tx + j*16;
            float s = acc[i][j] * SCALE - (1.0f - mr[i]*mc[j]) * 1e12f;
            Crow[col] = s;
        }
    }
}

// ---------------------------------------------------------------------------
// Batched NN GEMM: O[b,s,h] = sum_t Wgt[b,s,t] * V[b,t,h]
// ---------------------------------------------------------------------------
__global__ __launch_bounds__(256) void gemm_nn_kernel(
    const float* __restrict__ Wgt, const float* __restrict__ V,
    float* __restrict__ O)
{
    __shared__ float As[BK][BM + PAD];
    __shared__ float Bs[BK][BN + PAD];

    const int b = blockIdx.z;
    const float* A  = Wgt + (size_t)b * SEQ * SEQ;   // [SEQ, SEQ] K-major
    const float* Bv = V   + (size_t)b * SEQ * HID;   // [SEQ(K), HID(N)] N-major
    float* C = O + (size_t)b * SEQ * HID;
    const int M = SEQ, N = HID, K = SEQ;

    const int bm = blockIdx.y * BM;
    const int bn = blockIdx.x * BN;
    const int tid = threadIdx.x;

    const int ldrow = tid >> 1;
    const int ldk   = (tid & 1) << 2;
    const float* Ap = A + (size_t)(bm + ldrow) * K + ldk;

    const int brow  = tid >> 5;          // 0..7  (k row within tile)
    const int bcol4 = (tid & 31) << 2;   // 0..124
    const float* Bp = Bv + (size_t)brow * N + bn + bcol4;

    const int ty = tid >> 4;
    const int tx = tid & 15;

    float acc[8][8];
    #pragma unroll
    for (int i = 0; i < 8; i++)
        #pragma unroll
        for (int j = 0; j < 8; j++) acc[i][j] = 0.f;

    for (int k0 = 0; k0 < K; k0 += BK) {
        float4 av = *reinterpret_cast<const float4*>(Ap + k0);
        float4 bv4 = *reinterpret_cast<const float4*>(Bp + (size_t)k0 * N);
        As[ldk+0][ldrow] = av.x; As[ldk+1][ldrow] = av.y;
        As[ldk+2][ldrow] = av.z; As[ldk+3][ldrow] = av.w;
        *reinterpret_cast<float4*>(&Bs[brow][bcol4]) = bv4;
        __syncthreads();
        #pragma unroll
        for (int kk = 0; kk < BK; kk++) {
            float a[8], bb[8];
            float4 a0 = *reinterpret_cast<const float4*>(&As[kk][ty*8]);
            float4 a1 = *reinterpret_cast<const float4*>(&As[kk][ty*8+4]);
            a[0]=a0.x; a[1]=a0.y; a[2]=a0.z; a[3]=a0.w;
            a[4]=a1.x; a[5]=a1.y; a[6]=a1.z; a[7]=a1.w;
            #pragma unroll
            for (int j = 0; j < 8; j++) bb[j] = Bs[kk][tx + j*16];
            #pragma unroll
            for (int i = 0; i < 8; i++)
                #pragma unroll
                for (int j = 0; j < 8; j++)
                    acc[i][j] = fmaf(a[i], bb[j], acc[i][j]);
        }
        __syncthreads();
    }

    #pragma unroll
    for (int i = 0; i < 8; i++) {
        const int row = bm + ty*8 + i;
        float* Crow = C + (size_t)row * N;
        #pragma unroll
        for (int j = 0; j < 8; j++)
            Crow[bn + tx + j*16] = acc[i][j];
    }
}

// ---------------------------------------------------------------------------
// Row softmax over t (len SEQ) with mask multiply. One block per (b,row).
// ---------------------------------------------------------------------------
__global__ __launch_bounds__(256) void softmax_kernel(
    float* __restrict__ Sc, const int* __restrict__ mask)
{
    const int b = blockIdx.y, row = blockIdx.x, tid = threadIdx.x;
    float* srow = Sc + ((size_t)b * SEQ + row) * SEQ;
    const int* mrow = mask + (size_t)b * SEQ;

    float4 x = *reinterpret_cast<const float4*>(srow + tid*4);

    float mx = fmaxf(fmaxf(x.x, x.y), fmaxf(x.z, x.w));
    #pragma unroll
    for (int o = 16; o > 0; o >>= 1)
        mx = fmaxf(mx, __shfl_xor_sync(0xffffffffu, mx, o));

    __shared__ float red[8];
    if ((tid & 31) == 0) red[tid >> 5] = mx;
    __syncthreads();
    float rmx = red[0];
    #pragma unroll
    for (int i = 1; i < 8; i++) rmx = fmaxf(rmx, red[i]);

    float e0 = expf(x.x - rmx), e1 = expf(x.y - rmx);
    float e2 = expf(x.z - rmx), e3 = expf(x.w - rmx);
    float s = e0 + e1 + e2 + e3;
    #pragma unroll
    for (int o = 16; o > 0; o >>= 1)
        s += __shfl_xor_sync(0xffffffffu, s, o);
    __syncthreads();
    if ((tid & 31) == 0) red[tid >> 5] = s;
    __syncthreads();
    float tot = red[0];
    #pragma unroll
    for (int i = 1; i < 8; i++) tot += red[i];

    const float c = (1.0f / tot) * (float)mrow[row];
    float4 o4;
    o4.x = e0 * c * (float)mrow[tid*4 + 0];
    o4.y = e1 * c * (float)mrow[tid*4 + 1];
    o4.z = e2 * c * (float)mrow[tid*4 + 2];
    o4.w = e3 * c * (float)mrow[tid*4 + 3];
    *reinterpret_cast<float4*>(srow + tid*4) = o4;
}

// ---------------------------------------------------------------------------
extern "C" void kernel_launch(void* const* d_in, const int* in_sizes, int n_in,
                              void* d_out, int out_size)
{
    const float* x    = (const float*)d_in[0];
    const int*   mask = (const int*)  d_in[1];
    const float* Wq = (const float*)d_in[2];
    const float* bq = (const float*)d_in[3];
    const float* Wk = (const float*)d_in[4];
    const float* bk = (const float*)d_in[5];
    const float* Wv = (const float*)d_in[6];
    const float* bv = (const float*)d_in[7];
    const float* W1 = (const float*)d_in[8];
    const float* b1 = (const float*)d_in[9];
    const float* W2 = (const float*)d_in[10];
    const float* b2 = (const float*)d_in[11];
    float* out = (float*)d_out;

    float *q, *k, *v, *sc, *o, *h1;
    cudaGetSymbolAddress((void**)&q,  g_q);
    cudaGetSymbolAddress((void**)&k,  g_k);
    cudaGetSymbolAddress((void**)&v,  g_v);
    cudaGetSymbolAddress((void**)&sc, g_sc);
    cudaGetSymbolAddress((void**)&o,  g_o);
    cudaGetSymbolAddress((void**)&h1, g_h1);

    dim3 blk(256);
    const int M = NB * SEQ;                 // 16384
    dim3 gproj(HID / BN, M / BM);           // (6, 128)

    gemm_nt_kernel<<<gproj, blk>>>(x, Wq, bq, nullptr, q, M, HID, HID, 1);
    gemm_nt_kernel<<<gproj, blk>>>(x, Wk, bk, nullptr, k, M, HID, HID, 1);
    gemm_nt_kernel<<<gproj, blk>>>(x, Wv, bv, nullptr, v, M, HID, HID, 0);

    dim3 gsc(SEQ / BN, SEQ / BM, NB);       // (8, 8, 16)
    score_gemm_kernel<<<gsc, blk>>>(q, k, mask, sc);

    softmax_kernel<<<dim3(SEQ, NB), blk>>>(sc, mask);

    dim3 gwv(HID / BN, SEQ / BM, NB);       // (6, 8, 16)
    gemm_nn_kernel<<<gwv, blk>>>(sc, v, o);

    gemm_nt_kernel<<<gproj, blk>>>(o,  W1, b1, nullptr, h1, M, HID, HID, 1);
    gemm_nt_kernel<<<gproj, blk>>>(h1, W2, b2, o,      out, M, HID, HID, 0);
}